// round 1
// baseline (speedup 1.0000x reference)
#include <cuda_runtime.h>
#include <cstdint>

#define NU 30000
#define NI 30000
#define NN 60000
#define NRELS 10
#define NBAS 8
#define DIM 128
#define D4 32
#define NEDGE 1000000
#define NBATCH 256
#define SEQL 50

// ---------------- device scratch (static, no runtime alloc) ----------------
__device__ float4 g_Witem[NRELS * NI * D4];   // [r][item][d4]  ~154MB
__device__ float4 g_social[NU * D4];          // users only     ~15MB
__device__ float4 g_pooled[NI * D4];          // items only     ~15MB
__device__ int    g_cntDR[NU * NRELS];
__device__ int    g_pcnt[NI];
__device__ float  g_e[NBATCH * SEQL];

__device__ __forceinline__ void red4(float4* p, float4 v) {
    asm volatile("red.global.add.v4.f32 [%0], {%1,%2,%3,%4};"
        :: "l"(p), "f"(v.x), "f"(v.y), "f"(v.z), "f"(v.w) : "memory");
}

// ---------------- K0: zero accumulators ----------------
__global__ void k_zero() {
    int i = blockIdx.x * 256 + threadIdx.x;
    float4 z = make_float4(0.f, 0.f, 0.f, 0.f);
    if (i < NU * D4) { g_social[i] = z; g_pooled[i] = z; }
    if (i < NU * NRELS) g_cntDR[i] = 0;
    if (i < NI) g_pcnt[i] = 0;
}

// ---------------- K1: per-(dst,rel) counts and per-src counts ----------------
__global__ void k_count(const int* __restrict__ edst, const int* __restrict__ etyp,
                        const int* __restrict__ esrc) {
    int e = blockIdx.x * 256 + threadIdx.x;
    if (e >= NEDGE) return;
    int dst = edst[e], rel = etyp[e], si = esrc[e] - NU;
    if ((unsigned)dst < NU && (unsigned)rel < NRELS)
        atomicAdd(&g_cntDR[dst * NRELS + rel], 1);
    if ((unsigned)si < NI)
        atomicAdd(&g_pcnt[si], 1);
}

// ---------------- K2: Witem[r][i][:] = sum_b comp[r][b]*basis[b][NU+i][:] ----------------
__global__ void k_witem(const float* __restrict__ basis, const float* __restrict__ comp) {
    __shared__ float sc[NRELS * NBAS];
    if (threadIdx.x < NRELS * NBAS) sc[threadIdx.x] = comp[threadIdx.x];
    __syncthreads();
    int w = (blockIdx.x * blockDim.x + threadIdx.x) >> 5;
    int lane = threadIdx.x & 31;
    if (w >= NI) return;
    const float4* b4 = (const float4*)basis;
    float4 vb[NBAS];
#pragma unroll
    for (int b = 0; b < NBAS; b++)
        vb[b] = b4[(b * NN + NU + w) * D4 + lane];
#pragma unroll
    for (int r = 0; r < NRELS; r++) {
        float4 a = make_float4(0.f, 0.f, 0.f, 0.f);
#pragma unroll
        for (int b = 0; b < NBAS; b++) {
            float c = sc[r * NBAS + b];
            a.x += c * vb[b].x; a.y += c * vb[b].y;
            a.z += c * vb[b].z; a.w += c * vb[b].w;
        }
        g_Witem[(r * NI + w) * D4 + lane] = a;
    }
}

// ---------------- K3: scatter Witem[rel,src]/cnt(dst,rel) into social[dst] ----------------
__global__ void k_social(const int* __restrict__ edst, const int* __restrict__ etyp,
                         const int* __restrict__ esrc) {
    int w = (blockIdx.x * blockDim.x + threadIdx.x) >> 5;
    int lane = threadIdx.x & 31;
    if (w >= NEDGE) return;
    int dst = __ldg(edst + w), rel = __ldg(etyp + w);
    int si = __ldg(esrc + w) - NU;
    if ((unsigned)dst >= NU || (unsigned)rel >= NRELS || (unsigned)si >= NI) return;
    int c = g_cntDR[dst * NRELS + rel];
    float inv = 1.0f / (float)max(c, 1);
    float4 v = g_Witem[(rel * NI + si) * D4 + lane];
    v.x *= inv; v.y *= inv; v.z *= inv; v.w *= inv;
    red4(&g_social[dst * D4 + lane], v);
}

// ---------------- K4: social += root + bias ----------------
__global__ void k_socfin(const float* __restrict__ root, const float* __restrict__ bias) {
    int i = blockIdx.x * 256 + threadIdx.x;
    if (i >= NU * D4) return;
    const float4* r4 = (const float4*)root;
    const float4* b4 = (const float4*)bias;
    float4 s = g_social[i];
    float4 r = r4[i];                 // users are node rows [0, NU)
    float4 b = b4[i & (D4 - 1)];
    s.x += r.x + b.x; s.y += r.y + b.y; s.z += r.z + b.z; s.w += r.w + b.w;
    g_social[i] = s;
}

// ---------------- K5: scatter social[dst] into pooled[src] ----------------
__global__ void k_pooled(const int* __restrict__ edst, const int* __restrict__ esrc) {
    int w = (blockIdx.x * blockDim.x + threadIdx.x) >> 5;
    int lane = threadIdx.x & 31;
    if (w >= NEDGE) return;
    int dst = __ldg(edst + w);
    int si = __ldg(esrc + w) - NU;
    if ((unsigned)dst >= NU || (unsigned)si >= NI) return;
    float4 v = g_social[dst * D4 + lane];
    red4(&g_pooled[si * D4 + lane], v);
}

// ---------------- K6: pooled /= max(pcnt,1) ----------------
__global__ void k_poolfin() {
    int i = blockIdx.x * 256 + threadIdx.x;
    if (i >= NI * D4) return;
    float inv = 1.0f / fmaxf((float)g_pcnt[i >> 5], 1.0f);
    float4 p = g_pooled[i];
    p.x *= inv; p.y *= inv; p.z *= inv; p.w *= inv;
    g_pooled[i] = p;
}

// ---------------- K7: h = gathered pooled (masked);  e = tanh(h@A)·b ----------------
__global__ void __launch_bounds__(128) k_h_e(const int* __restrict__ ctx,
                                             const float* __restrict__ attn_a,
                                             const float* __restrict__ attn_b,
                                             float* __restrict__ hout) {
    extern __shared__ float sA[];            // 128*128 floats = 64KB
    __shared__ float sh[DIM];
    __shared__ float sred[4];
    int t = threadIdx.x;
    for (int i = t; i < DIM * DIM; i += blockDim.x) sA[i] = attn_a[i];
    float bb = attn_b[t];
    __syncthreads();
    const float* pooled = (const float*)g_pooled;
    for (int slot = blockIdx.x; slot < NBATCH * SEQL; slot += gridDim.x) {
        int id = ctx[slot];
        bool valid = (id >= NU) && (id < NN) && (g_pcnt[id - NU] > 0);
        float hv = valid ? pooled[(id - NU) * DIM + t] : 0.f;
        hout[slot * DIM + t] = hv;
        sh[t] = hv;
        __syncthreads();
        float s = 0.f;
#pragma unroll 16
        for (int d = 0; d < DIM; d++) s += sh[d] * sA[d * DIM + t];
        float te = tanhf(s) * bb;
#pragma unroll
        for (int o = 16; o; o >>= 1) te += __shfl_down_sync(0xffffffffu, te, o);
        if ((t & 31) == 0) sred[t >> 5] = te;
        __syncthreads();
        if (t == 0)
            g_e[slot] = valid ? (sred[0] + sred[1] + sred[2] + sred[3]) : -1e9f;
        __syncthreads();
    }
}

// ---------------- K8: softmax, rep, fc1->relu->fc2->relu ----------------
__global__ void __launch_bounds__(128) k_final(const float* __restrict__ h,
                                               const float* __restrict__ fc1w,
                                               const float* __restrict__ fc1b,
                                               const float* __restrict__ fc2w,
                                               const float* __restrict__ fc2b,
                                               float* __restrict__ proj) {
    int b = blockIdx.x, t = threadIdx.x;
    __shared__ float sattn[SEQL];
    __shared__ float srep[DIM];
    __shared__ float sx[DIM];
    if (t == 0) {
        float m = -3e38f;
        for (int l = 0; l < SEQL; l++) m = fmaxf(m, g_e[b * SEQL + l]);
        float s = 0.f;
        for (int l = 0; l < SEQL; l++) {
            float ev = g_e[b * SEQL + l];
            float x = (ev <= -0.5e9f) ? 0.f : expf(ev - m);
            sattn[l] = x; s += x;
        }
        float inv = (s > 0.f) ? 1.f / s : 0.f;
        for (int l = 0; l < SEQL; l++) sattn[l] *= inv;
    }
    __syncthreads();
    float r = 0.f;
    for (int l = 0; l < SEQL; l++) r += sattn[l] * h[(b * SEQL + l) * DIM + t];
    srep[t] = r;
    __syncthreads();
    float x = fc1b[t];
    for (int d = 0; d < DIM; d++) x += srep[d] * fc1w[t * DIM + d];
    x = fmaxf(x, 0.f);
    sx[t] = x;
    __syncthreads();
    float p = fc2b[t];
    for (int d = 0; d < DIM; d++) p += sx[d] * fc2w[t * DIM + d];
    proj[b * DIM + t] = fmaxf(p, 0.f);
}

// ---------------- launch ----------------
extern "C" void kernel_launch(void* const* d_in, const int* in_sizes, int n_in,
                              void* d_out, int out_size) {
    const int*   ctx    = (const int*)d_in[0];
    const int*   esrc   = (const int*)d_in[1];
    const int*   edst   = (const int*)d_in[2];
    const int*   etyp   = (const int*)d_in[3];
    const float* basis  = (const float*)d_in[4];
    const float* comp   = (const float*)d_in[5];
    const float* root   = (const float*)d_in[6];
    const float* bias   = (const float*)d_in[7];
    const float* attn_a = (const float*)d_in[8];
    const float* attn_b = (const float*)d_in[9];
    const float* fc1w   = (const float*)d_in[10];
    const float* fc1b   = (const float*)d_in[11];
    const float* fc2w   = (const float*)d_in[12];
    const float* fc2b   = (const float*)d_in[13];

    float* proj = (float*)d_out;
    float* hout = proj + NBATCH * DIM;

    cudaFuncSetAttribute(k_h_e, cudaFuncAttributeMaxDynamicSharedMemorySize,
                         DIM * DIM * (int)sizeof(float));

    k_zero<<<(NU * D4 + 255) / 256, 256>>>();
    k_count<<<(NEDGE + 255) / 256, 256>>>(edst, etyp, esrc);
    k_witem<<<(NI * 32 + 255) / 256, 256>>>(basis, comp);
    k_social<<<(NEDGE * 32 + 255) / 256, 256>>>(edst, etyp, esrc);
    k_socfin<<<(NU * D4 + 255) / 256, 256>>>(root, bias);
    k_pooled<<<(NEDGE * 32 + 255) / 256, 256>>>(edst, esrc);
    k_poolfin<<<(NI * D4 + 255) / 256, 256>>>();
    k_h_e<<<640, 128, DIM * DIM * (int)sizeof(float)>>>(ctx, attn_a, attn_b, hout);
    k_final<<<NBATCH, 128>>>(hout, fc1w, fc1b, fc2w, fc2b, proj);
}